// round 6
// baseline (speedup 1.0000x reference)
#include <cuda_runtime.h>

#define W 512
#define H 512
#define BATCH 32
#define IMG (H * W)
#define NTOT (BATCH * IMG)
#define FULLM 0xffffffffu
#define NW 4

#define HS1 32
#define NSTRIP1 (H / HS1)
#define HS2 64
#define NSTRIP2 (H / HS2)

// Static device scratch (allocation-free rule): single intermediate buffer
// holding both tensors after 3 skeleton iterations (pred @0, target @NTOT).
__device__ float g_skel[2 * NTOT];
__device__ double g_acc;

__device__ __forceinline__ float4 ld4(const float* p) {
    return *reinterpret_cast<const float4*>(p);
}
__device__ __forceinline__ float4 f4all(float v) { return make_float4(v, v, v, v); }

__global__ void zero_acc_k() { g_acc = 0.0; }
__global__ void finalize_k(float* out) {
    out[0] = (float)(g_acc * (1.0 / (double)NTOT));
}

// ---------------------------------------------------------------------------
// One soft-skeletonize stage as a streaming register pipeline element.
//   m = minpool3x3(x) (pad +inf); M = maxpool3x3(m) (pad -inf);
//   out = relu(x - relu(M - m)), emitted with a 2-row latency.
// ---------------------------------------------------------------------------
struct SkelStage {
    float4 rm1, rm2;            // row-min history (rows srow-1, srow-2)
    float rl1, rl2, rr1, rr2;   // halo row-min history (cols cbase-1 / cbase+4)
    float4 x1, x2;              // input history
    float4 m1;                  // min-pool output at row srow-2
    float4 q1, q2;              // row-max(m) history
};

__device__ __forceinline__ void stage_init(SkelStage& S) {
    const float PINF = __int_as_float(0x7f800000);
    const float NINF = __int_as_float(0xff800000);
    S.rm1 = S.rm2 = f4all(PINF);
    S.rl1 = S.rl2 = S.rr1 = S.rr2 = PINF;
    S.x1 = S.x2 = f4all(PINF);
    S.m1 = f4all(NINF);
    S.q1 = S.q2 = f4all(NINF);
}

// v + x-halos are for input row `srow` (caller supplies PINF when row invalid).
// Returns candidate output for row srow-2 (caller checks range before use).
__device__ __forceinline__ float4 stage_step(SkelStage& S, float4 v,
    float hlz, float hlw, float hrx, float hry,
    int srow, int lane, bool leftEdge, bool rightEdge)
{
    const float NINF = __int_as_float(0xff800000);

    // horizontal min (row srow)
    float lf = __shfl_up_sync(FULLM, v.w, 1);
    float rt = __shfl_down_sync(FULLM, v.x, 1);
    if (lane == 0)  lf = hlw;
    if (lane == 31) rt = hrx;
    float t01 = fminf(v.x, v.y), t12 = fminf(v.y, v.z), t23 = fminf(v.z, v.w);
    float4 rm0;
    rm0.x = fminf(lf, t01);
    rm0.y = fminf(t01, v.z);
    rm0.z = fminf(t12, v.w);
    rm0.w = fminf(t23, rt);
    float rl0 = fminf(fminf(hlz, hlw), v.x);
    float rr0 = fminf(fminf(v.w, hrx), hry);

    // vertical min -> m at row srow-1
    float4 m0;
    m0.x = fminf(fminf(rm0.x, S.rm1.x), S.rm2.x);
    m0.y = fminf(fminf(rm0.y, S.rm1.y), S.rm2.y);
    m0.z = fminf(fminf(rm0.z, S.rm1.z), S.rm2.z);
    m0.w = fminf(fminf(rm0.w, S.rm1.w), S.rm2.w);
    float mL = fminf(fminf(rl0, S.rl1), S.rl2);
    float mR = fminf(fminf(rr0, S.rr1), S.rr2);
    int mrow = srow - 1;
    if (mrow < 0 || mrow >= H) { m0 = f4all(NINF); mL = NINF; mR = NINF; }

    // horizontal max of m (row srow-1)
    float mlf = __shfl_up_sync(FULLM, m0.w, 1);
    float mrt = __shfl_down_sync(FULLM, m0.x, 1);
    if (lane == 0)  mlf = leftEdge  ? NINF : mL;
    if (lane == 31) mrt = rightEdge ? NINF : mR;
    float u01 = fmaxf(m0.x, m0.y), u12 = fmaxf(m0.y, m0.z), u23 = fmaxf(m0.z, m0.w);
    float4 q0;
    q0.x = fmaxf(mlf, u01);
    q0.y = fmaxf(u01, m0.z);
    q0.z = fmaxf(u12, m0.w);
    q0.w = fmaxf(u23, mrt);

    // vertical max -> M at row srow-2; out = relu(x - relu(M - m))
    float4 o;
    o.x = fmaxf(S.x2.x - fmaxf(fmaxf(fmaxf(q0.x, S.q1.x), S.q2.x) - S.m1.x, 0.0f), 0.0f);
    o.y = fmaxf(S.x2.y - fmaxf(fmaxf(fmaxf(q0.y, S.q1.y), S.q2.y) - S.m1.y, 0.0f), 0.0f);
    o.z = fmaxf(S.x2.z - fmaxf(fmaxf(fmaxf(q0.z, S.q1.z), S.q2.z) - S.m1.z, 0.0f), 0.0f);
    o.w = fmaxf(S.x2.w - fmaxf(fmaxf(fmaxf(q0.w, S.q1.w), S.q2.w) - S.m1.w, 0.0f), 0.0f);

    // shift rolling windows
    S.x2 = S.x1; S.x1 = v;
    S.rm2 = S.rm1; S.rm1 = rm0;
    S.rl2 = S.rl1; S.rl1 = rl0;
    S.rr2 = S.rr1; S.rr1 = rr0;
    S.m1 = m0;
    S.q2 = S.q1; S.q1 = q0;
    return o;
}

// ---------------------------------------------------------------------------
// Kernel 1: skeleton iterations 1-3 fused. Stage k input row = s - 3(k-1)
// (1-iteration stagger so cross-warp halos come from the PREVIOUS loop
// iteration's smem slot: one __syncthreads per row, no intra-row chain).
// ---------------------------------------------------------------------------
__global__ void __launch_bounds__(128, 3) skel3_k(
    const float* __restrict__ pred, const float* __restrict__ targ)
{
    const float PINF = __int_as_float(0x7f800000);
    __shared__ float pub[2][2][NW][4];   // [slot][stage out 1|2][warp][x,y,z,w-edge vals]

    int lane = threadIdx.x & 31;
    int warp = threadIdx.x >> 5;
    int strip = blockIdx.x, b = blockIdx.y, t = blockIdx.z;
    const float* src = (t == 0 ? pred : targ) + (size_t)b * IMG;
    float* dst = g_skel + (size_t)t * NTOT + (size_t)b * IMG;

    int cbase = warp * 128 + lane * 4;
    bool leftEdge = (cbase == 0);
    bool rightEdge = (cbase + 4 == W);
    int r0 = strip * HS1;

    SkelStage S1, S2, S3;
    stage_init(S1); stage_init(S2); stage_init(S3);
    float4 d1 = f4all(PINF), d2 = f4all(PINF);

    const float* rowp = src + (size_t)(r0 - 6) * W + cbase;
    float* orowp = dst + (size_t)r0 * W + cbase;

    #pragma unroll 1
    for (int s = r0 - 6; s <= r0 + HS1 + 7; ++s) {
        int p = s & 1, q = p ^ 1;

        // ---- stage 1: load row s with gmem halos
        float4 v1;
        float hlz = PINF, hlw = PINF, hrx = PINF, hry = PINF;
        if (s >= 0 && s < H) {
            v1 = ld4(rowp);
            if (lane == 0 && !leftEdge)   { float2 h = *(const float2*)(rowp - 2); hlz = h.x; hlw = h.y; }
            if (lane == 31 && !rightEdge) { float2 h = *(const float2*)(rowp + 4); hrx = h.x; hry = h.y; }
        } else v1 = f4all(PINF);
        rowp += W;
        float4 o1 = stage_step(S1, v1, hlz, hlw, hrx, hry, s, lane, leftEdge, rightEdge);

        // ---- stage 2: input row s-3, halos from prev-iteration smem
        int r2 = s - 3;
        float4 v2;
        float a2lz = PINF, a2lw = PINF, a2rx = PINF, a2ry = PINF;
        if (r2 >= 0 && r2 < H) {
            v2 = d1;
            if (warp > 0)      { a2lz = pub[q][0][warp - 1][2]; a2lw = pub[q][0][warp - 1][3]; }
            if (warp < NW - 1) { a2rx = pub[q][0][warp + 1][0]; a2ry = pub[q][0][warp + 1][1]; }
        } else v2 = f4all(PINF);
        float4 o2 = stage_step(S2, v2, a2lz, a2lw, a2rx, a2ry, r2, lane, leftEdge, rightEdge);

        // ---- stage 3: input row s-6
        int r3 = s - 6;
        float4 v3;
        float a3lz = PINF, a3lw = PINF, a3rx = PINF, a3ry = PINF;
        if (r3 >= 0 && r3 < H) {
            v3 = d2;
            if (warp > 0)      { a3lz = pub[q][1][warp - 1][2]; a3lw = pub[q][1][warp - 1][3]; }
            if (warp < NW - 1) { a3rx = pub[q][1][warp + 1][0]; a3ry = pub[q][1][warp + 1][1]; }
        } else v3 = f4all(PINF);
        float4 o3 = stage_step(S3, v3, a3lz, a3lw, a3rx, a3ry, r3, lane, leftEdge, rightEdge);

        int orow = s - 8;
        if (orow >= r0 && orow < r0 + HS1) {
            *reinterpret_cast<float4*>(orowp) = o3;
            orowp += W;
        }

        // ---- publish this iteration's boundary values for next iteration
        if (lane == 0) {
            pub[p][0][warp][0] = o1.x; pub[p][0][warp][1] = o1.y;
            pub[p][1][warp][0] = o2.x; pub[p][1][warp][1] = o2.y;
        }
        if (lane == 31) {
            pub[p][0][warp][2] = o1.z; pub[p][0][warp][3] = o1.w;
            pub[p][1][warp][2] = o2.z; pub[p][1][warp][3] = o2.w;
        }
        d1 = o1; d2 = o2;
        __syncthreads();
    }
}

__device__ __forceinline__ float pixel_loss(float a, float bv, float na, float nb) {
    float ds = a - bv;
    float l = 0.6f * ds * ds;
    bool ona = a > 0.5f, onb = bv > 0.5f;
    bool ea = (na == 2.0f) && ona;
    bool eb = (nb == 2.0f) && onb;
    if (ea != eb) l += 0.2f;
    bool ca = (na >= 4.0f) && ona;
    bool cb = (nb >= 4.0f) && onb;
    if (ca != cb) l += 0.2f;
    return l;
}

// ---------------------------------------------------------------------------
// Kernel 2: skeleton iterations 4-5 + full loss, BOTH tensors per block.
// Stage A input row s; stage B row s-3 (skeleton emitted at row s-5);
// loss folds skeleton row s-6 into 3x3 sum-pool and emits loss row s-7.
// Skeleton is never written to HBM.
// ---------------------------------------------------------------------------
__global__ void __launch_bounds__(128, 2) skel2_loss_k()
{
    const float PINF = __int_as_float(0x7f800000);
    __shared__ float pubA[2][2][NW][4];  // stage-A outputs  [slot][tensor][warp][4]
    __shared__ float pubS[2][2][NW][2];  // skeleton edges   [slot][tensor][warp][lane0.x, lane31.w]
    __shared__ float wred[NW];

    int lane = threadIdx.x & 31;
    int warp = threadIdx.x >> 5;
    int strip = blockIdx.x, b = blockIdx.y;
    const float* src[2];
    src[0] = g_skel + (size_t)b * IMG;
    src[1] = g_skel + (size_t)NTOT + (size_t)b * IMG;

    int cbase = warp * 128 + lane * 4;
    bool leftEdge = (cbase == 0);
    bool rightEdge = (cbase + 4 == W);
    int r0 = strip * HS2;

    SkelStage SA[2], SB[2];
    float4 dA[2], dS[2];
    #pragma unroll
    for (int t = 0; t < 2; ++t) {
        stage_init(SA[t]); stage_init(SB[t]);
        dA[t] = f4all(PINF);
        dS[t] = f4all(0.0f);
    }

    // loss rolling state
    float4 sp1 = f4all(0), sp2 = f4all(0), st1 = f4all(0), st2 = f4all(0);
    float4 vp1 = f4all(0), vt1 = f4all(0);
    float acc = 0.0f;

    const float* rowp0 = src[0] + (size_t)(r0 - 5) * W + cbase;
    const float* rowp1 = src[1] + (size_t)(r0 - 5) * W + cbase;

    #pragma unroll 1
    for (int s = r0 - 5; s <= r0 + HS2 + 6; ++s) {
        int p = s & 1, q = p ^ 1;
        float4 oB[2];

        #pragma unroll
        for (int t = 0; t < 2; ++t) {
            const float* rowp = (t == 0) ? rowp0 : rowp1;

            // stage A: load row s
            float4 vA;
            float hlz = PINF, hlw = PINF, hrx = PINF, hry = PINF;
            if (s >= 0 && s < H) {
                vA = ld4(rowp);
                if (lane == 0 && !leftEdge)   { float2 h = *(const float2*)(rowp - 2); hlz = h.x; hlw = h.y; }
                if (lane == 31 && !rightEdge) { float2 h = *(const float2*)(rowp + 4); hrx = h.x; hry = h.y; }
            } else vA = f4all(PINF);
            float4 oA = stage_step(SA[t], vA, hlz, hlw, hrx, hry, s, lane, leftEdge, rightEdge);

            // stage B: input row s-3
            int rB = s - 3;
            float4 vB;
            float blz = PINF, blw = PINF, brx = PINF, bry = PINF;
            if (rB >= 0 && rB < H) {
                vB = dA[t];
                if (warp > 0)      { blz = pubA[q][t][warp - 1][2]; blw = pubA[q][t][warp - 1][3]; }
                if (warp < NW - 1) { brx = pubA[q][t][warp + 1][0]; bry = pubA[q][t][warp + 1][1]; }
            } else vB = f4all(PINF);
            oB[t] = stage_step(SB[t], vB, blz, blw, brx, bry, rB, lane, leftEdge, rightEdge);

            dA[t] = oA;
            if (lane == 0) {
                pubA[p][t][warp][0] = oA.x; pubA[p][t][warp][1] = oA.y;
                pubS[p][t][warp][0] = oB[t].x;
            }
            if (lane == 31) {
                pubA[p][t][warp][2] = oA.z; pubA[p][t][warp][3] = oA.w;
                pubS[p][t][warp][1] = oB[t].w;
            }
        }
        rowp0 += W; rowp1 += W;

        // ---- loss stage: fold skeleton row rs = s-6 (zero pad outside image)
        int rs = s - 6;
        float4 kp, kt;
        float pL = 0.f, pR = 0.f, tL = 0.f, tR = 0.f;
        if (rs >= 0 && rs < H) {
            kp = dS[0]; kt = dS[1];
            if (warp > 0)      { pL = pubS[q][0][warp - 1][1]; tL = pubS[q][1][warp - 1][1]; }
            if (warp < NW - 1) { pR = pubS[q][0][warp + 1][0]; tR = pubS[q][1][warp + 1][0]; }
        } else { kp = f4all(0); kt = f4all(0); }

        float lfp = __shfl_up_sync(FULLM, kp.w, 1);
        float rtp = __shfl_down_sync(FULLM, kp.x, 1);
        if (lane == 0)  lfp = pL;
        if (lane == 31) rtp = pR;
        float4 sp0;
        sp0.x = lfp + kp.x + kp.y;
        sp0.y = kp.x + kp.y + kp.z;
        sp0.z = kp.y + kp.z + kp.w;
        sp0.w = kp.z + kp.w + rtp;

        float lft = __shfl_up_sync(FULLM, kt.w, 1);
        float rtt = __shfl_down_sync(FULLM, kt.x, 1);
        if (lane == 0)  lft = tL;
        if (lane == 31) rtt = tR;
        float4 st0;
        st0.x = lft + kt.x + kt.y;
        st0.y = kt.x + kt.y + kt.z;
        st0.z = kt.y + kt.z + kt.w;
        st0.w = kt.z + kt.w + rtt;

        int lrow = s - 7;
        if (lrow >= r0 && lrow < r0 + HS2) {
            acc += pixel_loss(vp1.x, vt1.x, sp0.x + sp1.x + sp2.x, st0.x + st1.x + st2.x);
            acc += pixel_loss(vp1.y, vt1.y, sp0.y + sp1.y + sp2.y, st0.y + st1.y + st2.y);
            acc += pixel_loss(vp1.z, vt1.z, sp0.z + sp1.z + sp2.z, st0.z + st1.z + st2.z);
            acc += pixel_loss(vp1.w, vt1.w, sp0.w + sp1.w + sp2.w, st0.w + st1.w + st2.w);
        }

        sp2 = sp1; sp1 = sp0;
        st2 = st1; st1 = st0;
        vp1 = kp; vt1 = kt;
        dS[0] = oB[0]; dS[1] = oB[1];
        __syncthreads();
    }

    // block reduction of loss contributions
    #pragma unroll
    for (int o = 16; o > 0; o >>= 1)
        acc += __shfl_xor_sync(FULLM, acc, o);
    if (lane == 0) wred[warp] = acc;
    __syncthreads();
    if (threadIdx.x == 0) {
        float bsum = wred[0] + wred[1] + wred[2] + wred[3];
        atomicAdd(&g_acc, (double)bsum);
    }
}

extern "C" void kernel_launch(void* const* d_in, const int* in_sizes, int n_in,
                              void* d_out, int out_size)
{
    const float* pred = (const float*)d_in[0];
    const float* targ = (const float*)d_in[1];
    float* out = (float*)d_out;

    zero_acc_k<<<1, 1>>>();
    skel3_k<<<dim3(NSTRIP1, BATCH, 2), 128>>>(pred, targ);
    skel2_loss_k<<<dim3(NSTRIP2, BATCH), 128>>>();
    finalize_k<<<1, 1>>>(out);
}

// round 7
// speedup vs baseline: 1.2390x; 1.2390x over previous
#include <cuda_runtime.h>

#define W 512
#define H 512
#define BATCH 32
#define IMG (H * W)
#define NTOT (BATCH * IMG)
#define HS 16
#define NSTRIP (H / HS)
#define FULLM 0xffffffffu

// Static device scratch (allocation-free rule): two ping-pong buffers holding
// both tensors (pred at offset 0, target at offset NTOT).
__device__ float g_b0[2 * NTOT];
__device__ float g_b1[2 * NTOT];
__device__ double g_acc;

__device__ __forceinline__ float4 ld4(const float* p) {
    return *reinterpret_cast<const float4*>(p);
}
__device__ __forceinline__ float4 f4all(float v) { return make_float4(v, v, v, v); }

__global__ void zero_acc_k() { g_acc = 0.0; }
__global__ void finalize_k(float* out) {
    out[0] = (float)(g_acc * (1.0 / (double)NTOT));
}

// ---------------------------------------------------------------------------
// Kernel: one soft-skeletonize iteration (validated R4 version, unroll 2).
//   m = minpool3x3(x) (pad +inf); M = maxpool3x3(m) (pad -inf);
//   x' = relu(x - relu(M - m))
// Register-streaming: warp owns 128 cols (4/lane float4), rolling 3-row windows.
// ---------------------------------------------------------------------------
__global__ void __launch_bounds__(128) skel_iter(
    const float* __restrict__ extA, const float* __restrict__ extB,
    int srcSel, int dstSel)
{
    const float PINF = __int_as_float(0x7f800000);
    const float NINF = __int_as_float(0xff800000);
    int lane = threadIdx.x & 31;
    int warp = threadIdx.x >> 5;
    int strip = blockIdx.x;
    int b = blockIdx.y;
    int t = blockIdx.z;

    const float* src;
    if (srcSel == 0)      src = (t == 0 ? extA : extB);
    else if (srcSel == 1) src = g_b0 + (size_t)t * NTOT;
    else                  src = g_b1 + (size_t)t * NTOT;
    float* dst = (dstSel == 1 ? g_b0 : g_b1) + (size_t)t * NTOT;

    const float* sp = src + (size_t)b * IMG;
    float* dp = dst + (size_t)b * IMG;

    int cbase = warp * 128 + lane * 4;
    bool leftEdge = (cbase == 0);
    bool rightEdge = (cbase + 4 == W);
    int r0 = strip * HS;

    float4 x1, x2;
    float4 rm0, rm1, rm2;
    float rl1, rl2, rr1, rr2;
    float4 m1;
    float4 q0, q1, q2;

    x1 = x2 = f4all(PINF);
    rm1 = rm2 = f4all(PINF);
    rl1 = rl2 = rr1 = rr2 = PINF;
    m1 = f4all(NINF);
    q1 = q2 = f4all(NINF);

    const float* rowp = sp + (size_t)(r0 - 2) * W + cbase;
    float* orowp = dp + (size_t)r0 * W + cbase;

    #pragma unroll 2
    for (int s = r0 - 2; s <= r0 + HS + 1; ++s) {
        float4 v;
        float hlz = PINF, hlw = PINF, hrx = PINF, hry = PINF;
        if (s >= 0 && s < H) {
            v = ld4(rowp);
            if (lane == 0 && !leftEdge)  { float4 h = ld4(rowp - 4); hlz = h.z; hlw = h.w; }
            if (lane == 31 && !rightEdge){ float4 h = ld4(rowp + 4); hrx = h.x; hry = h.y; }
        } else {
            v = f4all(PINF);
        }
        rowp += W;

        float lf = __shfl_up_sync(FULLM, v.w, 1);
        float rt = __shfl_down_sync(FULLM, v.x, 1);
        if (lane == 0)  lf = hlw;
        if (lane == 31) rt = hrx;
        rm0.x = fminf(fminf(lf,  v.x), v.y);
        rm0.y = fminf(fminf(v.x, v.y), v.z);
        rm0.z = fminf(fminf(v.y, v.z), v.w);
        rm0.w = fminf(fminf(v.z, v.w), rt);
        float rl0 = fminf(fminf(hlz, hlw), v.x);
        float rr0 = fminf(fminf(v.w, hrx), hry);

        float4 m0;
        m0.x = fminf(fminf(rm0.x, rm1.x), rm2.x);
        m0.y = fminf(fminf(rm0.y, rm1.y), rm2.y);
        m0.z = fminf(fminf(rm0.z, rm1.z), rm2.z);
        m0.w = fminf(fminf(rm0.w, rm1.w), rm2.w);
        float mL = fminf(fminf(rl0, rl1), rl2);
        float mR = fminf(fminf(rr0, rr1), rr2);
        int mrow = s - 1;
        if (mrow < 0 || mrow >= H) { m0 = f4all(NINF); mL = NINF; mR = NINF; }

        float mlf = __shfl_up_sync(FULLM, m0.w, 1);
        float mrt = __shfl_down_sync(FULLM, m0.x, 1);
        if (lane == 0)  mlf = leftEdge  ? NINF : mL;
        if (lane == 31) mrt = rightEdge ? NINF : mR;
        q0.x = fmaxf(fmaxf(mlf,  m0.x), m0.y);
        q0.y = fmaxf(fmaxf(m0.x, m0.y), m0.z);
        q0.z = fmaxf(fmaxf(m0.y, m0.z), m0.w);
        q0.w = fmaxf(fmaxf(m0.z, m0.w), mrt);

        int orow = s - 2;
        if (orow >= r0) {
            float Mx = fmaxf(fmaxf(q0.x, q1.x), q2.x);
            float My = fmaxf(fmaxf(q0.y, q1.y), q2.y);
            float Mz = fmaxf(fmaxf(q0.z, q1.z), q2.z);
            float Mw = fmaxf(fmaxf(q0.w, q1.w), q2.w);
            float4 o;
            o.x = fmaxf(x2.x - fmaxf(Mx - m1.x, 0.0f), 0.0f);
            o.y = fmaxf(x2.y - fmaxf(My - m1.y, 0.0f), 0.0f);
            o.z = fmaxf(x2.z - fmaxf(Mz - m1.z, 0.0f), 0.0f);
            o.w = fmaxf(x2.w - fmaxf(Mw - m1.w, 0.0f), 0.0f);
            *reinterpret_cast<float4*>(orowp) = o;
            orowp += W;
        }

        x2 = x1; x1 = v;
        rm2 = rm1; rm1 = rm0;
        rl2 = rl1; rl1 = rl0;
        rr2 = rr1; rr1 = rr0;
        m1 = m0;
        q2 = q1; q1 = q0;
    }
}

// ---------------------------------------------------------------------------
// Skeleton stage with EXTENDED column halos: besides interior cols [0,128)
// of the warp strip, also produces the skeleton value at relative cols -1
// (meaningful on lane 0) and 128 (lane 31), recomputed from gmem halo loads
// (bit-identical to neighbor warp's interior — min/max/relu are exact).
// ---------------------------------------------------------------------------
struct SkelStageH {
    float4 rm1, rm2;           // interior row-min history
    float rl1, rl2;            // rowmin col -1 history
    float rlb1, rlb2;          // rowmin col -2 history
    float rr1, rr2;            // rowmin col 128 history
    float rrb1, rrb2;          // rowmin col 129 history
    float4 x1, x2;             // interior input history
    float xL1, xL2, xR1, xR2;  // input col -1 / col 128 history
    float4 m1;                 // interior m (1-row delay)
    float mLp, mRp;            // m col -1 / col 128 (1-row delay)
    float4 q1, q2;             // interior rowmax(m) history
    float qL1, qL2, qR1, qR2;  // halo rowmax(m) history
};

__device__ __forceinline__ void stageh_init(SkelStageH& S) {
    const float PINF = __int_as_float(0x7f800000);
    const float NINF = __int_as_float(0xff800000);
    S.rm1 = S.rm2 = f4all(PINF);
    S.rl1 = S.rl2 = S.rlb1 = S.rlb2 = PINF;
    S.rr1 = S.rr2 = S.rrb1 = S.rrb2 = PINF;
    S.x1 = S.x2 = f4all(PINF);
    S.xL1 = S.xL2 = S.xR1 = S.xR2 = PINF;
    S.m1 = f4all(NINF);
    S.mLp = S.mRp = NINF;
    S.q1 = S.q2 = f4all(NINF);
    S.qL1 = S.qL2 = S.qR1 = S.qR2 = NINF;
}

// v: input row srow cols [lane*4, lane*4+4); hl: cols -4..-1 (lane0);
// hr: cols 128..131 (lane31). Outputs for row srow-2: interior o, halo oL/oR.
__device__ __forceinline__ void stageh_step(SkelStageH& S, float4 v, float4 hl, float4 hr,
    int srow, int lane, bool leftEdge, bool rightEdge,
    float4& o, float& oL, float& oR)
{
    const float NINF = __int_as_float(0xff800000);

    // horizontal min (row srow)
    float lf = __shfl_up_sync(FULLM, v.w, 1);
    float rt = __shfl_down_sync(FULLM, v.x, 1);
    if (lane == 0)  lf = hl.w;
    if (lane == 31) rt = hr.x;
    float4 rm0;
    rm0.x = fminf(fminf(lf,  v.x), v.y);
    rm0.y = fminf(fminf(v.x, v.y), v.z);
    rm0.z = fminf(fminf(v.y, v.z), v.w);
    rm0.w = fminf(fminf(v.z, v.w), rt);
    float rl0  = fminf(fminf(hl.z, hl.w), v.x);   // rowmin col -1
    float rlb0 = fminf(fminf(hl.y, hl.z), hl.w);  // rowmin col -2
    float rr0  = fminf(fminf(v.w, hr.x), hr.y);   // rowmin col 128
    float rrb0 = fminf(fminf(hr.x, hr.y), hr.z);  // rowmin col 129

    // vertical min -> m at row srow-1
    float4 m0;
    m0.x = fminf(fminf(rm0.x, S.rm1.x), S.rm2.x);
    m0.y = fminf(fminf(rm0.y, S.rm1.y), S.rm2.y);
    m0.z = fminf(fminf(rm0.z, S.rm1.z), S.rm2.z);
    m0.w = fminf(fminf(rm0.w, S.rm1.w), S.rm2.w);
    float mL  = fminf(fminf(rl0,  S.rl1),  S.rl2);
    float mLb = fminf(fminf(rlb0, S.rlb1), S.rlb2);
    float mR  = fminf(fminf(rr0,  S.rr1),  S.rr2);
    float mRb = fminf(fminf(rrb0, S.rrb1), S.rrb2);
    int mrow = srow - 1;
    if (mrow < 0 || mrow >= H) {
        m0 = f4all(NINF); mL = mLb = mR = mRb = NINF;
    }

    // horizontal max of m (row srow-1)
    float mlf = __shfl_up_sync(FULLM, m0.w, 1);
    float mrt = __shfl_down_sync(FULLM, m0.x, 1);
    if (lane == 0)  mlf = leftEdge  ? NINF : mL;
    if (lane == 31) mrt = rightEdge ? NINF : mR;
    float4 q0;
    q0.x = fmaxf(fmaxf(mlf,  m0.x), m0.y);
    q0.y = fmaxf(fmaxf(m0.x, m0.y), m0.z);
    q0.z = fmaxf(fmaxf(m0.y, m0.z), m0.w);
    q0.w = fmaxf(fmaxf(m0.z, m0.w), mrt);
    float qL0 = fmaxf(fmaxf(mLb, mL), m0.x);   // q at col -1 (lane0 view)
    float qR0 = fmaxf(fmaxf(m0.w, mR), mRb);   // q at col 128 (lane31 view)

    // vertical max -> M at row srow-2; out = relu(x - relu(M - m))
    float Mx = fmaxf(fmaxf(q0.x, S.q1.x), S.q2.x);
    float My = fmaxf(fmaxf(q0.y, S.q1.y), S.q2.y);
    float Mz = fmaxf(fmaxf(q0.z, S.q1.z), S.q2.z);
    float Mw = fmaxf(fmaxf(q0.w, S.q1.w), S.q2.w);
    o.x = fmaxf(S.x2.x - fmaxf(Mx - S.m1.x, 0.0f), 0.0f);
    o.y = fmaxf(S.x2.y - fmaxf(My - S.m1.y, 0.0f), 0.0f);
    o.z = fmaxf(S.x2.z - fmaxf(Mz - S.m1.z, 0.0f), 0.0f);
    o.w = fmaxf(S.x2.w - fmaxf(Mw - S.m1.w, 0.0f), 0.0f);
    float ML = fmaxf(fmaxf(qL0, S.qL1), S.qL2);
    float MR = fmaxf(fmaxf(qR0, S.qR1), S.qR2);
    oL = fmaxf(S.xL2 - fmaxf(ML - S.mLp, 0.0f), 0.0f);
    oR = fmaxf(S.xR2 - fmaxf(MR - S.mRp, 0.0f), 0.0f);

    // shift rolling windows
    S.x2 = S.x1; S.x1 = v;
    S.xL2 = S.xL1; S.xL1 = hl.w;
    S.xR2 = S.xR1; S.xR1 = hr.x;
    S.rm2 = S.rm1; S.rm1 = rm0;
    S.rl2 = S.rl1;  S.rl1 = rl0;
    S.rlb2 = S.rlb1; S.rlb1 = rlb0;
    S.rr2 = S.rr1;  S.rr1 = rr0;
    S.rrb2 = S.rrb1; S.rrb1 = rrb0;
    S.m1 = m0; S.mLp = mL; S.mRp = mR;
    S.q2 = S.q1; S.q1 = q0;
    S.qL2 = S.qL1; S.qL1 = qL0;
    S.qR2 = S.qR1; S.qR1 = qR0;
}

__device__ __forceinline__ float pixel_loss(float a, float bv, float na, float nb) {
    float ds = a - bv;
    float l = 0.6f * ds * ds;
    bool ona = a > 0.5f, onb = bv > 0.5f;
    bool ea = (na == 2.0f) && ona;
    bool eb = (nb == 2.0f) && onb;
    if (ea != eb) l += 0.2f;
    bool ca = (na >= 4.0f) && ona;
    bool cb = (nb >= 4.0f) && onb;
    if (ca != cb) l += 0.2f;
    return l;
}

// ---------------------------------------------------------------------------
// Kernel: skeleton iteration 5 + full loss, both tensors per block, fully
// warp-independent (no smem exchange, no in-loop __syncthreads). Reads
// iter-4 output from g_b1; skeleton is never written back to HBM.
// Row pipeline: ingest row s -> skeleton row ks=s-2 -> loss row l=ks-1=s-3.
// ---------------------------------------------------------------------------
__global__ void __launch_bounds__(128) skel5_loss_k()
{
    const float PINF = __int_as_float(0x7f800000);
    int lane = threadIdx.x & 31;
    int warp = threadIdx.x >> 5;
    int strip = blockIdx.x, b = blockIdx.y;
    const float* src0 = g_b1 + (size_t)b * IMG;
    const float* src1 = g_b1 + (size_t)NTOT + (size_t)b * IMG;

    int cbase = warp * 128 + lane * 4;
    bool leftEdge = (cbase == 0);
    bool rightEdge = (cbase + 4 == W);
    int r0 = strip * HS;

    SkelStageH SA, SB;
    stageh_init(SA); stageh_init(SB);

    // loss rolling state
    float4 sp1 = f4all(0), sp2 = f4all(0), st1 = f4all(0), st2 = f4all(0);
    float4 vp1 = f4all(0), vt1 = f4all(0);
    float acc = 0.0f;

    const float* rp0 = src0 + (size_t)(r0 - 3) * W + cbase;
    const float* rp1 = src1 + (size_t)(r0 - 3) * W + cbase;

    #pragma unroll 1
    for (int s = r0 - 3; s <= r0 + HS + 2; ++s) {
        bool inrow = (s >= 0 && s < H);

        // ---- tensor 0 (pred)
        float4 v0 = f4all(PINF), hl0 = f4all(PINF), hr0 = f4all(PINF);
        if (inrow) {
            v0 = ld4(rp0);
            if (lane == 0 && !leftEdge)   hl0 = ld4(rp0 - 4);
            if (lane == 31 && !rightEdge) hr0 = ld4(rp0 + 4);
        }
        // ---- tensor 1 (target)
        float4 v1 = f4all(PINF), hl1 = f4all(PINF), hr1 = f4all(PINF);
        if (inrow) {
            v1 = ld4(rp1);
            if (lane == 0 && !leftEdge)   hl1 = ld4(rp1 - 4);
            if (lane == 31 && !rightEdge) hr1 = ld4(rp1 + 4);
        }
        rp0 += W; rp1 += W;

        float4 o0, o1; float oL0, oR0, oL1, oR1;
        stageh_step(SA, v0, hl0, hr0, s, lane, leftEdge, rightEdge, o0, oL0, oR0);
        stageh_step(SB, v1, hl1, hr1, s, lane, leftEdge, rightEdge, o1, oL1, oR1);

        // ---- skeleton row ks (zero outside image / before pipeline validity)
        int ks = s - 2;
        bool kv = (ks >= 0 && ks < H);
        float4 kp = kv ? o0 : f4all(0);
        float4 kt = kv ? o1 : f4all(0);
        float hpL = (kv && !leftEdge)  ? oL0 : 0.0f;
        float hpR = (kv && !rightEdge) ? oR0 : 0.0f;
        float htL = (kv && !leftEdge)  ? oL1 : 0.0f;
        float htR = (kv && !rightEdge) ? oR1 : 0.0f;

        // ---- 3x3 sum-pool row sums (zero pad)
        float lfp = __shfl_up_sync(FULLM, kp.w, 1);
        float rtp = __shfl_down_sync(FULLM, kp.x, 1);
        if (lane == 0)  lfp = hpL;
        if (lane == 31) rtp = hpR;
        float4 sp0;
        sp0.x = lfp + kp.x + kp.y;
        sp0.y = kp.x + kp.y + kp.z;
        sp0.z = kp.y + kp.z + kp.w;
        sp0.w = kp.z + kp.w + rtp;

        float lft = __shfl_up_sync(FULLM, kt.w, 1);
        float rtt = __shfl_down_sync(FULLM, kt.x, 1);
        if (lane == 0)  lft = htL;
        if (lane == 31) rtt = htR;
        float4 st0;
        st0.x = lft + kt.x + kt.y;
        st0.y = kt.x + kt.y + kt.z;
        st0.z = kt.y + kt.z + kt.w;
        st0.w = kt.z + kt.w + rtt;

        // ---- emit loss row l = ks-1
        int lrow = s - 3;
        if (lrow >= r0 && lrow < r0 + HS) {
            acc += pixel_loss(vp1.x, vt1.x, sp0.x + sp1.x + sp2.x, st0.x + st1.x + st2.x);
            acc += pixel_loss(vp1.y, vt1.y, sp0.y + sp1.y + sp2.y, st0.y + st1.y + st2.y);
            acc += pixel_loss(vp1.z, vt1.z, sp0.z + sp1.z + sp2.z, st0.z + st1.z + st2.z);
            acc += pixel_loss(vp1.w, vt1.w, sp0.w + sp1.w + sp2.w, st0.w + st1.w + st2.w);
        }

        sp2 = sp1; sp1 = sp0;
        st2 = st1; st1 = st0;
        vp1 = kp; vt1 = kt;
    }

    // block reduction
    #pragma unroll
    for (int o = 16; o > 0; o >>= 1)
        acc += __shfl_xor_sync(FULLM, acc, o);
    __shared__ float ws[4];
    if (lane == 0) ws[warp] = acc;
    __syncthreads();
    if (threadIdx.x == 0) {
        float bsum = ws[0] + ws[1] + ws[2] + ws[3];
        atomicAdd(&g_acc, (double)bsum);
    }
}

extern "C" void kernel_launch(void* const* d_in, const int* in_sizes, int n_in,
                              void* d_out, int out_size)
{
    const float* pred = (const float*)d_in[0];
    const float* targ = (const float*)d_in[1];
    float* out = (float*)d_out;

    dim3 git(NSTRIP, BATCH, 2);
    dim3 gfl(NSTRIP, BATCH);

    zero_acc_k<<<1, 1>>>();
    // skeleton iterations 1-4, ping-pong: d_in -> b0 -> b1 -> b0 -> b1
    skel_iter<<<git, 128>>>(pred, targ, 0, 1);
    skel_iter<<<git, 128>>>(nullptr, nullptr, 1, 2);
    skel_iter<<<git, 128>>>(nullptr, nullptr, 2, 1);
    skel_iter<<<git, 128>>>(nullptr, nullptr, 1, 2);
    // iteration 5 + sum-pool + comparisons + weighted MSE, fused
    skel5_loss_k<<<gfl, 128>>>();
    finalize_k<<<1, 1>>>(out);
}